// round 7
// baseline (speedup 1.0000x reference)
#include <cuda_runtime.h>

// Staggered parallel transport, 8 paths, 32^4 lattice — fused, warp-specialized.
//
// Layouts (row-major, metadata order):
//   d_in[0] x_re : (8, V, 3) float    d_in[1] x_im : (8, V, 3)
//   d_in[2] U_re : (4, V, 9) float    d_in[3] U_im : (4, V, 9)
//   d_out        : (2, 8, V, 3) float   (re block then im block)
// site s = ((x*32 + y)*32 + z)*32 + t
//
// Channels:
//   0: copy            1: fwd mu=0       2: fwd mu=1   3: fwd mu=2
//   4: fwd mu=3        5: bwd mu=0 (scatter)   6: bwd mu=1 (scatter)
//   7: fwd mu=0 then fwd mu=1  — first hop in SMEM (y-tiled block + halo)
//
// Block = 512 threads over a 256-site tile (t:32 × y:8 at fixed x,z).
//   Role A (tid<256):  phase1: U0 group (ch1, ch5, ch7-hop1 -> smem, halo)
//                      phase2: ch0 copy, ch3 (U2)
//   Role B (tid>=256): phase1: ch4 (U3), pre-issue U1/x2/x6 loads
//                      phase2: ch2, ch6 (scatter), ch7 final from smem
// One __syncthreads() separates tmp_s production (A) from consumption (B).

#define VOL (32 * 32 * 32 * 32)

__device__ __forceinline__ void mv(const float* __restrict__ Ur,
                                   const float* __restrict__ Ui,
                                   const float* vr, const float* vi,
                                   float sgn, float* yr, float* yi) {
#pragma unroll
    for (int a = 0; a < 3; a++) {
        float sr = 0.f, si = 0.f;
#pragma unroll
        for (int b = 0; b < 3; b++) {
            float ur = Ur[a * 3 + b], ui = Ui[a * 3 + b];
            sr = fmaf(ur, vr[b], sr);
            sr = fmaf(-ui, vi[b], sr);
            si = fmaf(ur, vi[b], si);
            si = fmaf(ui, vr[b], si);
        }
        yr[a] = sgn * sr;
        yi[a] = sgn * si;
    }
}

__device__ __forceinline__ void mvdag(const float* __restrict__ Ur,
                                      const float* __restrict__ Ui,
                                      const float* vr, const float* vi,
                                      float sgn, float* yr, float* yi) {
#pragma unroll
    for (int a = 0; a < 3; a++) {
        float sr = 0.f, si = 0.f;
#pragma unroll
        for (int b = 0; b < 3; b++) {
            float ur = Ur[b * 3 + a], ui = Ui[b * 3 + a];  // conj-transpose
            sr = fmaf(ur, vr[b], sr);
            sr = fmaf(ui, vi[b], sr);
            si = fmaf(ur, vi[b], si);
            si = fmaf(-ui, vr[b], si);
        }
        yr[a] = sgn * sr;
        yi[a] = sgn * si;
    }
}

__device__ __forceinline__ void ldv(const float* __restrict__ xr,
                                    const float* __restrict__ xi,
                                    int ch, int s, float* vr, float* vi) {
    int b = (ch * VOL + s) * 3;
#pragma unroll
    for (int c = 0; c < 3; c++) {
        vr[c] = __ldg(xr + b + c);
        vi[c] = __ldg(xi + b + c);
    }
}

__device__ __forceinline__ void ldU(const float* __restrict__ Ur,
                                    const float* __restrict__ Ui,
                                    int mu, int s, float* ur, float* ui) {
    int b = (mu * VOL + s) * 9;
#pragma unroll
    for (int k = 0; k < 9; k++) {
        ur[k] = __ldg(Ur + b + k);
        ui[k] = __ldg(Ui + b + k);
    }
}

__device__ __forceinline__ void stv(float* __restrict__ out, int ch, int s,
                                    const float* yr, const float* yi) {
    int br = (ch * VOL + s) * 3;
    int bi = ((8 + ch) * VOL + s) * 3;
#pragma unroll
    for (int c = 0; c < 3; c++) {
        out[br + c] = yr[c];
        out[bi + c] = yi[c];
    }
}

__global__ void __launch_bounds__(512)
k_fused(const float* __restrict__ xr, const float* __restrict__ xi,
        const float* __restrict__ Ur, const float* __restrict__ Ui,
        float* __restrict__ out) {
    // smem tmp for ch7 first hop: [component 0..5][y-row 0..8][t]
    __shared__ float tmp_s[6][9][32];

    int tid = threadIdx.x;
    int g = tid & 255;            // site index within tile
    int roleB = tid >> 8;         // 0 = role A, 1 = role B
    int t = g & 31;
    int yl = (g >> 5) & 7;        // 0..7

    int bid = blockIdx.x;         // 0..4095
    int y0 = (bid & 3) << 3;      // {0,8,16,24}
    int z = (bid >> 2) & 31;
    int x = bid >> 7;

    int y = y0 + yl;
    int s = (x << 15) | (y << 10) | (z << 5) | t;

    float vr[3], vi[3], yr[3], yi[3];

    if (!roleB) {
        // ================= Role A =================
        int s_px = (s & ~(31 << 15)) | (((x + 1) & 31) << 15);

        // ---- phase 1: mu = 0 group ----
        {
            float U0r[9], U0i[9];
            ldU(Ur, Ui, 0, s, U0r, U0i);

            // ch1: out1(s) = U0(s) x1(s + x_hat)     (eta0 = 1)
            ldv(xr, xi, 1, s_px, vr, vi);
            mv(U0r, U0i, vr, vi, 1.f, yr, yi);
            stv(out, 1, s, yr, yi);

            // ch5 (scatter): out5(s + x_hat) = U0^dag(s) x5(s)
            ldv(xr, xi, 5, s, vr, vi);
            mvdag(U0r, U0i, vr, vi, 1.f, yr, yi);
            stv(out, 5, s_px, yr, yi);

            // ch7 hop 1 -> smem: tmp(s) = U0(s) x7(s + x_hat)
            ldv(xr, xi, 7, s_px, vr, vi);
            mv(U0r, U0i, vr, vi, 1.f, yr, yi);
#pragma unroll
            for (int c = 0; c < 3; c++) {
                tmp_s[c][yl][t] = yr[c];
                tmp_s[3 + c][yl][t] = yi[c];
            }

            // halo row y0+8 (one warp, reuses U0 register arrays)
            if (yl == 0) {
                int yh = (y0 + 8) & 31;
                int sh = (x << 15) | (yh << 10) | (z << 5) | t;
                int sh_px = (sh & ~(31 << 15)) | (((x + 1) & 31) << 15);
                ldU(Ur, Ui, 0, sh, U0r, U0i);
                ldv(xr, xi, 7, sh_px, vr, vi);
                mv(U0r, U0i, vr, vi, 1.f, yr, yi);
#pragma unroll
                for (int c = 0; c < 3; c++) {
                    tmp_s[c][8][t] = yr[c];
                    tmp_s[3 + c][8][t] = yi[c];
                }
            }
        }

        __syncthreads();

        // ---- phase 2: ch0 copy + ch3 (mu=2) ----
        ldv(xr, xi, 0, s, vr, vi);
        stv(out, 0, s, vr, vi);

        {
            float eta2 = ((x ^ y) & 1) ? -1.f : 1.f;  // (-1)^(x+y)
            int s_pz = (s & ~(31 << 5)) | (((z + 1) & 31) << 5);
            float U2r[9], U2i[9];
            ldU(Ur, Ui, 2, s, U2r, U2i);
            ldv(xr, xi, 3, s_pz, vr, vi);
            mv(U2r, U2i, vr, vi, eta2, yr, yi);
            stv(out, 3, s, yr, yi);
        }
    } else {
        // ================= Role B =================
        int s_py = (s & ~(31 << 10)) | (((y + 1) & 31) << 10);
        float eta1 = (x & 1) ? -1.f : 1.f;  // (-1)^x

        // ---- phase 1: ch4 (mu=3) ----
        {
            float eta3 = ((x ^ y ^ z) & 1) ? -1.f : 1.f;  // (-1)^(x+y+z)
            int s_pt = (s & ~31) | ((t + 1) & 31);
            float U3r[9], U3i[9];
            ldU(Ur, Ui, 3, s, U3r, U3i);
            ldv(xr, xi, 4, s_pt, vr, vi);
            mv(U3r, U3i, vr, vi, eta3, yr, yi);
            stv(out, 4, s, yr, yi);
        }

        // pre-issue U1 + x2 + x6 loads before the barrier (latency overlap)
        float U1r[9], U1i[9];
        ldU(Ur, Ui, 1, s, U1r, U1i);
        float v2r[3], v2i[3], v6r[3], v6i[3];
        ldv(xr, xi, 2, s_py, v2r, v2i);
        ldv(xr, xi, 6, s, v6r, v6i);

        __syncthreads();

        // ---- phase 2: mu = 1 group ----
        // ch2: out2(s) = eta1(s) U1(s) x2(s + y_hat)
        mv(U1r, U1i, v2r, v2i, eta1, yr, yi);
        stv(out, 2, s, yr, yi);

        // ch6 (scatter): out6(s + y_hat) = eta1(s) U1^dag(s) x6(s)
        mvdag(U1r, U1i, v6r, v6i, eta1, yr, yi);
        stv(out, 6, s_py, yr, yi);

        // ch7: out7(s) = eta1(s) U1(s) tmp(s + y_hat)   [smem]
#pragma unroll
        for (int c = 0; c < 3; c++) {
            vr[c] = tmp_s[c][yl + 1][t];
            vi[c] = tmp_s[3 + c][yl + 1][t];
        }
        mv(U1r, U1i, vr, vi, eta1, yr, yi);
        stv(out, 7, s, yr, yi);
    }
}

extern "C" void kernel_launch(void* const* d_in, const int* in_sizes, int n_in,
                              void* d_out, int out_size) {
    const float* xr = (const float*)d_in[0];
    const float* xi = (const float*)d_in[1];
    const float* Ur = (const float*)d_in[2];
    const float* Ui = (const float*)d_in[3];
    float* out = (float*)d_out;

    k_fused<<<4096, 512>>>(xr, xi, Ur, Ui, out);
}